// round 2
// baseline (speedup 1.0000x reference)
#include <cuda_runtime.h>
#include <math.h>

#define B_   32
#define S_   1024
#define IN_  1024
#define H_   1024

// ---------------- device scratch (no allocation allowed) ----------------
__device__ float    g_H[2][B_][H_];      // ping-pong hidden state, 256 KB
__device__ unsigned g_flags[4][32];      // per batch-group arrival flags

// ---------------- sync helpers ----------------
__device__ __forceinline__ unsigned ld_acq(const unsigned* p) {
    unsigned v;
    asm volatile("ld.global.acquire.gpu.u32 %0, [%1];" : "=r"(v) : "l"(p));
    return v;
}
__device__ __forceinline__ void st_rel(unsigned* p, unsigned v) {
    asm volatile("st.global.release.gpu.u32 [%0], %1;" :: "l"(p), "r"(v));
}

// ---------------- init: zero H0 and flags ----------------
__global__ void rnn_init_kernel() {
    int idx = blockIdx.x * blockDim.x + threadIdx.x;
    int stride = gridDim.x * blockDim.x;
    float* p = &g_H[0][0][0];
    for (int i = idx; i < 2 * B_ * H_; i += stride) p[i] = 0.0f;
    if (idx < 128) ((unsigned*)g_flags)[idx] = 0u;
}

// ---------------- Xp = X @ W_xh + b  (fp32 SGEMM, 128x128x8 tiles) ----------------
__global__ void __launch_bounds__(256) gemm_xp_kernel(
    const float* __restrict__ A,    // [32768, 1024]
    const float* __restrict__ Bm,   // [1024, 1024]
    const float* __restrict__ bias, // [1024]
    float* __restrict__ C)          // [32768, 1024]
{
    __shared__ float As[8][128];    // transposed A tile
    __shared__ float Bs[8][128];

    int tid  = threadIdx.x;
    int brow = blockIdx.y * 128;
    int bcol = blockIdx.x * 128;

    int arow = tid >> 1;            // 0..127
    int acol = (tid & 1) * 4;       // 0 or 4
    int brl  = tid >> 5;            // 0..7
    int bc4  = (tid & 31) * 4;      // 0..124

    int ty = tid >> 4;              // 0..15
    int tx = tid & 15;              // 0..15

    float acc[8][8];
#pragma unroll
    for (int i = 0; i < 8; i++)
#pragma unroll
        for (int j = 0; j < 8; j++) acc[i][j] = 0.0f;

    const float* Aptr = A + (size_t)(brow + arow) * IN_ + acol;
    const float* Bptr = Bm + (size_t)brl * H_ + bcol + bc4;

    for (int k0 = 0; k0 < IN_; k0 += 8) {
        float4 a = *(const float4*)(Aptr + k0);
        As[acol + 0][arow] = a.x;
        As[acol + 1][arow] = a.y;
        As[acol + 2][arow] = a.z;
        As[acol + 3][arow] = a.w;
        *(float4*)&Bs[brl][bc4] = *(const float4*)(Bptr + (size_t)k0 * H_);
        __syncthreads();

#pragma unroll
        for (int k = 0; k < 8; k++) {
            float ar[8], br[8];
            *(float4*)(ar)     = *(float4*)&As[k][ty * 4];
            *(float4*)(ar + 4) = *(float4*)&As[k][64 + ty * 4];
            *(float4*)(br)     = *(float4*)&Bs[k][tx * 4];
            *(float4*)(br + 4) = *(float4*)&Bs[k][64 + tx * 4];
#pragma unroll
            for (int i = 0; i < 8; i++)
#pragma unroll
                for (int j = 0; j < 8; j++)
                    acc[i][j] = fmaf(ar[i], br[j], acc[i][j]);
        }
        __syncthreads();
    }

    // epilogue: add bias, store
    float4 bv0 = *(const float4*)&bias[bcol + tx * 4];
    float4 bv1 = *(const float4*)&bias[bcol + 64 + tx * 4];
    float bb[8] = {bv0.x, bv0.y, bv0.z, bv0.w, bv1.x, bv1.y, bv1.z, bv1.w};

#pragma unroll
    for (int i = 0; i < 8; i++) {
        int m = brow + ((i < 4) ? (ty * 4 + i) : (64 + ty * 4 + (i - 4)));
        float4 o0, o1;
        o0.x = acc[i][0] + bb[0]; o0.y = acc[i][1] + bb[1];
        o0.z = acc[i][2] + bb[2]; o0.w = acc[i][3] + bb[3];
        o1.x = acc[i][4] + bb[4]; o1.y = acc[i][5] + bb[5];
        o1.z = acc[i][6] + bb[6]; o1.w = acc[i][7] + bb[7];
        *(float4*)&C[(size_t)m * H_ + bcol + tx * 4]      = o0;
        *(float4*)&C[(size_t)m * H_ + bcol + 64 + tx * 4] = o1;
    }
}

// ---------------- recurrent scan ----------------
// 128 CTAs = 4 batch-groups (8 batches each) x 32 col-groups (32 cols each).
// W_hh slice resident in SMEM; H rows staged per step; per-group flag barrier.
#define WS_STRIDE  1025
#define WS_FLOATS  (32 * WS_STRIDE)          // 32800
#define HS_FLOATS  (8 * H_)                  // 8192
#define RED_FLOATS (4 * 64)                  // 256
#define RNN_SMEM_BYTES ((WS_FLOATS + HS_FLOATS + RED_FLOATS) * 4)

extern __shared__ float rnn_smem[];

__global__ void __launch_bounds__(256, 1) rnn_kernel(
    const float* __restrict__ Whh,   // [1024, 1024] (k-major)
    float* __restrict__ out,         // [B, S, H] holds Xp on entry, H_t on exit
    int write_last)
{
    float* Ws  = rnn_smem;                       // [32][1025]  W_hh[:, j0+j]
    float* Hs  = rnn_smem + WS_FLOATS;           // [8][1024]
    float* red = rnn_smem + WS_FLOATS + HS_FLOATS; // [4][64]

    int tid = threadIdx.x;
    int cta = blockIdx.x;
    int bg  = cta >> 5;      // batch group 0..3
    int cg  = cta & 31;      // col group 0..31
    int b0  = bg * 8;
    int j0  = cg * 32;

    // Preload W_hh slice: Ws[j][k] = Whh[k][j0+j]. Coalesced global reads,
    // conflict-free SMEM stores (stride 1025).
    {
        int lane = tid & 31;
        int w    = tid >> 5;
        for (int k = w; k < H_; k += 8) {
            Ws[lane * WS_STRIDE + k] = Whh[(size_t)k * H_ + j0 + lane];
        }
    }

    int warp  = tid >> 5;
    int lane  = tid & 31;
    int jt    = warp >> 1;        // j-tile 0..3 (8 cols each)
    int khalf = warp & 1;         // k-half 0/1
    int kbase = khalf * 512;

    unsigned* myflags = g_flags[bg];

    const float* hp_base = Hs + kbase + lane;
    const float* wp_base = Ws + (jt * 8) * WS_STRIDE + kbase + lane;

    __syncthreads();   // Ws ready

    for (int t = 0; t < S_; t++) {
        // ---- stage H rows for our 8 batches (bypass L1: written by other CTAs) ----
        const float4* Hsrc = (const float4*)(&g_H[t & 1][b0][0]);
        float4* Hdst = (float4*)Hs;
        for (int i = tid; i < HS_FLOATS / 4; i += 256) {
            Hdst[i] = __ldcg(Hsrc + i);
        }
        __syncthreads();

        // ---- main loop: 8 batches x 8 cols per warp, lane-interleaved k ----
        float acc[8][8];
#pragma unroll
        for (int a = 0; a < 8; a++)
#pragma unroll
            for (int c = 0; c < 8; c++) acc[a][c] = 0.0f;

#pragma unroll
        for (int i = 0; i < 16; i++) {
            float h[8], wv[8];
#pragma unroll
            for (int bb = 0; bb < 8; bb++) h[bb] = hp_base[bb * H_ + i * 32];
#pragma unroll
            for (int jj = 0; jj < 8; jj++) wv[jj] = wp_base[jj * WS_STRIDE + i * 32];
#pragma unroll
            for (int bb = 0; bb < 8; bb++)
#pragma unroll
                for (int jj = 0; jj < 8; jj++)
                    acc[bb][jj] = fmaf(h[bb], wv[jj], acc[bb][jj]);
        }

        // ---- warp butterfly reduction over the 32 k-lanes ----
#pragma unroll
        for (int bb = 0; bb < 8; bb++)
#pragma unroll
            for (int jj = 0; jj < 8; jj++) {
                float v = acc[bb][jj];
                v += __shfl_xor_sync(0xffffffffu, v, 16);
                v += __shfl_xor_sync(0xffffffffu, v, 8);
                v += __shfl_xor_sync(0xffffffffu, v, 4);
                v += __shfl_xor_sync(0xffffffffu, v, 2);
                v += __shfl_xor_sync(0xffffffffu, v, 1);
                acc[bb][jj] = v;
            }

        // ---- combine the two k-half warps of each tile ----
        int id0 = lane, id1 = lane + 32;
        float v0 = acc[id0 >> 3][id0 & 7];
        float v1 = acc[id1 >> 3][id1 & 7];
        if (khalf == 1) {
            red[jt * 64 + id0] = v0;
            red[jt * 64 + id1] = v1;
        }
        __syncthreads();
        if (khalf == 0) {
            v0 += red[jt * 64 + id0];
            v1 += red[jt * 64 + id1];
#pragma unroll
            for (int s = 0; s < 2; s++) {
                int   id = (s == 0) ? id0 : id1;
                float v  = (s == 0) ? v0 : v1;
                int bb = id >> 3, jj = id & 7;
                int b = b0 + bb;
                int j = j0 + jt * 8 + jj;
                size_t o = ((size_t)(b * S_ + t)) * H_ + j;
                float val = tanhf(v + out[o]);   // out[o] currently holds Xp
                out[o] = val;                    // out_t = H_t
                g_H[(t + 1) & 1][b][j] = val;
                if (write_last && t == S_ - 1) {
                    out[(size_t)B_ * S_ * H_ + (size_t)b * H_ + j] = val;
                }
            }
        }

        // ---- per-batch-group barrier (flag array, release/acquire) ----
        __threadfence();
        __syncthreads();
        if (tid == 0) st_rel(&myflags[cg], (unsigned)(t + 1));
        if (tid < 32) {
            while (ld_acq(&myflags[tid]) < (unsigned)(t + 1)) { }
        }
        __syncthreads();
    }
}

// ---------------- launch ----------------
extern "C" void kernel_launch(void* const* d_in, const int* in_sizes, int n_in,
                              void* d_out, int out_size) {
    const float* X    = (const float*)d_in[0];
    const float* Wxh  = (const float*)d_in[1];
    const float* Whh  = (const float*)d_in[2];
    const float* bh   = (const float*)d_in[3];
    float* out        = (float*)d_out;

    rnn_init_kernel<<<64, 256>>>();

    dim3 gg(8, 256);
    gemm_xp_kernel<<<gg, 256>>>(X, Wxh, bh, out);

    cudaFuncSetAttribute(rnn_kernel,
                         cudaFuncAttributeMaxDynamicSharedMemorySize,
                         RNN_SMEM_BYTES);
    int write_last = (out_size >= B_ * S_ * H_ + B_ * H_) ? 1 : 0;
    rnn_kernel<<<128, 256, RNN_SMEM_BYTES>>>(Whh, out, write_last);
}

// round 3
// speedup vs baseline: 1.5771x; 1.5771x over previous
#include <cuda_runtime.h>
#include <math.h>

#define B_   32
#define S_   1024
#define IN_  1024
#define H_   1024

// ---------------- device scratch (no allocation allowed) ----------------
__device__ float    g_H[2][B_][H_];      // ping-pong hidden state
__device__ unsigned g_flags[4][32];      // per batch-group arrival flags (one 128B line per group)

// ---------------- helpers ----------------
__device__ __forceinline__ unsigned ld_acq(const unsigned* p) {
    unsigned v;
    asm volatile("ld.global.acquire.gpu.u32 %0, [%1];" : "=r"(v) : "l"(p));
    return v;
}
__device__ __forceinline__ void st_rel(unsigned* p, unsigned v) {
    asm volatile("st.global.release.gpu.u32 [%0], %1;" :: "l"(p), "r"(v));
}
__device__ __forceinline__ unsigned long long fma2(unsigned long long a,
                                                  unsigned long long b,
                                                  unsigned long long c) {
    unsigned long long d;
    asm("fma.rn.f32x2 %0, %1, %2, %3;" : "=l"(d) : "l"(a), "l"(b), "l"(c));
    return d;
}
__device__ __forceinline__ unsigned long long add2(unsigned long long a,
                                                   unsigned long long b) {
    unsigned long long d;
    asm("add.rn.f32x2 %0, %1, %2;" : "=l"(d) : "l"(a), "l"(b));
    return d;
}
__device__ __forceinline__ unsigned long long pack2(float x) {
    unsigned long long d;
    asm("mov.b64 %0, {%1, %1};" : "=l"(d) : "f"(x));
    return d;
}
__device__ __forceinline__ void unpack2(unsigned long long v, float& lo, float& hi) {
    asm("mov.b64 {%0, %1}, %2;" : "=f"(lo), "=f"(hi) : "l"(v));
}

// ---------------- init: zero H0 and flags ----------------
__global__ void rnn_init_kernel() {
    int idx = blockIdx.x * blockDim.x + threadIdx.x;
    int stride = gridDim.x * blockDim.x;
    float* p = &g_H[0][0][0];
    for (int i = idx; i < 2 * B_ * H_; i += stride) p[i] = 0.0f;
    if (idx < 128) ((unsigned*)g_flags)[idx] = 0u;
}

// ---------------- Xp = X @ W_xh + b  (fp32 SGEMM, 128x128x8 tiles, f32x2 FMA) ----------------
__global__ void __launch_bounds__(256, 2) gemm_xp_kernel(
    const float* __restrict__ A,    // [32768, 1024]
    const float* __restrict__ Bm,   // [1024, 1024]
    const float* __restrict__ bias, // [1024]
    float* __restrict__ C)          // [32768, 1024]
{
    __shared__ float As[8][128];    // transposed A tile
    __shared__ float Bs[8][128];

    int tid  = threadIdx.x;
    int brow = blockIdx.y * 128;
    int bcol = blockIdx.x * 128;

    int arow = tid >> 1;            // 0..127
    int acol = (tid & 1) * 4;       // 0 or 4
    int brl  = tid >> 5;            // 0..7
    int bc4  = (tid & 31) * 4;      // 0..124

    int ty = tid >> 4;              // 0..15
    int tx = tid & 15;              // 0..15

    unsigned long long acc2[8][4];
#pragma unroll
    for (int i = 0; i < 8; i++)
#pragma unroll
        for (int j = 0; j < 4; j++) acc2[i][j] = 0ull;

    const float* Aptr = A + (size_t)(brow + arow) * IN_ + acol;
    const float* Bptr = Bm + (size_t)brl * H_ + bcol + bc4;

    for (int k0 = 0; k0 < IN_; k0 += 8) {
        float4 a = *(const float4*)(Aptr + k0);
        As[acol + 0][arow] = a.x;
        As[acol + 1][arow] = a.y;
        As[acol + 2][arow] = a.z;
        As[acol + 3][arow] = a.w;
        *(float4*)&Bs[brl][bc4] = *(const float4*)(Bptr + (size_t)k0 * H_);
        __syncthreads();

#pragma unroll
        for (int k = 0; k < 8; k++) {
            float ar[8];
            *(float4*)(ar)     = *(float4*)&As[k][ty * 4];
            *(float4*)(ar + 4) = *(float4*)&As[k][64 + ty * 4];
            unsigned long long br2[4];
            br2[0] = *(const unsigned long long*)&Bs[k][tx * 4];
            br2[1] = *(const unsigned long long*)&Bs[k][tx * 4 + 2];
            br2[2] = *(const unsigned long long*)&Bs[k][64 + tx * 4];
            br2[3] = *(const unsigned long long*)&Bs[k][64 + tx * 4 + 2];
            unsigned long long ar2[8];
#pragma unroll
            for (int i = 0; i < 8; i++) ar2[i] = pack2(ar[i]);
#pragma unroll
            for (int i = 0; i < 8; i++)
#pragma unroll
                for (int j = 0; j < 4; j++)
                    acc2[i][j] = fma2(ar2[i], br2[j], acc2[i][j]);
        }
        __syncthreads();
    }

    // epilogue: add bias, store
    float4 bv0 = *(const float4*)&bias[bcol + tx * 4];
    float4 bv1 = *(const float4*)&bias[bcol + 64 + tx * 4];
    float bb[8] = {bv0.x, bv0.y, bv0.z, bv0.w, bv1.x, bv1.y, bv1.z, bv1.w};

#pragma unroll
    for (int i = 0; i < 8; i++) {
        int m = brow + ((i < 4) ? (ty * 4 + i) : (64 + ty * 4 + (i - 4)));
        float o[8];
        unpack2(acc2[i][0], o[0], o[1]);
        unpack2(acc2[i][1], o[2], o[3]);
        unpack2(acc2[i][2], o[4], o[5]);
        unpack2(acc2[i][3], o[6], o[7]);
        float4 o0, o1;
        o0.x = o[0] + bb[0]; o0.y = o[1] + bb[1];
        o0.z = o[2] + bb[2]; o0.w = o[3] + bb[3];
        o1.x = o[4] + bb[4]; o1.y = o[5] + bb[5];
        o1.z = o[6] + bb[6]; o1.w = o[7] + bb[7];
        *(float4*)&C[(size_t)m * H_ + bcol + tx * 4]      = o0;
        *(float4*)&C[(size_t)m * H_ + bcol + 64 + tx * 4] = o1;
    }
}

// ---------------- recurrent scan ----------------
// 128 CTAs = 4 batch-groups (8 batches each) x 32 col-groups (32 cols each).
// W_hh slice resident in SMEM (k-major, stride 34 -> conflict-free LDS.64 pairs).
// Per warp: 8 batches x 8 cols register tile, k split lane(32) x khalf(2).
#define WS_STRIDE  34
#define WS_FLOATS  (H_ * WS_STRIDE)          // 34816
#define HS_FLOATS  (8 * H_)                  // 8192
#define RED_STRIDE 72
#define RED_HALF   (4 * RED_STRIDE)          // 288
#define RED_FLOATS (2 * RED_HALF)            // 576
#define RNN_SMEM_BYTES ((WS_FLOATS + HS_FLOATS + RED_FLOATS) * 4)

extern __shared__ float rnn_smem[];

__global__ void __launch_bounds__(256, 1) rnn_kernel(
    const float* __restrict__ Whh,   // [1024, 1024]
    float* __restrict__ out,         // [B, S, H] holds Xp on entry, H_t on exit
    int write_last)
{
    float* Ws  = rnn_smem;                        // [1024][34]  Ws[k][j]
    float* Hs  = rnn_smem + WS_FLOATS;            // [8][1024]
    float* red = rnn_smem + WS_FLOATS + HS_FLOATS;// [2][4][72]

    int tid = threadIdx.x;
    int cta = blockIdx.x;
    int bg  = cta >> 5;      // batch group 0..3
    int cg  = cta & 31;      // col group 0..31
    int b0  = bg * 8;
    int j0  = cg * 32;

    // Preload W_hh slice: Ws[k][j] = Whh[k][j0+j] (k-major, stride 34).
    {
        int j = tid & 31;
        for (int k = tid >> 5; k < H_; k += 8)
            Ws[k * WS_STRIDE + j] = Whh[(size_t)k * H_ + j0 + j];
    }

    int warp  = tid >> 5;
    int lane  = tid & 31;
    int jt    = warp >> 1;        // j-tile 0..3 (8 cols each)
    int khalf = warp & 1;         // k-half 0/1
    int kbase = khalf * 512;

    unsigned* myflags = g_flags[bg];

    // consumer mapping: thread owns output (b0+cb, j0+cc)
    int cb = tid >> 5;            // 0..7
    int cc = tid & 31;            // 0..31
    int cjt = cc >> 3;
    int cid = cb * 8 + (cc & 7);
    size_t out_base = ((size_t)(b0 + cb) * S_) * H_ + j0 + cc;   // + t*H_ per step

    const float* hp = Hs + kbase + lane;
    const float* wp = Ws + (size_t)(kbase + lane) * WS_STRIDE + jt * 8;

    __syncthreads();   // Ws ready

    for (int t = 0; t < S_; t++) {
        // ---- prefetch Xp(t) for this thread's output (DRAM latency hidden by compute) ----
        float xr = __ldcg(&out[out_base + (size_t)t * H_]);

        // ---- stage H rows for our 8 batches (L2, bypass L1) ----
        {
            const float4* Hsrc = (const float4*)(&g_H[t & 1][b0][0]);
            float4* Hdst = (float4*)Hs;
#pragma unroll
            for (int i = 0; i < HS_FLOATS / 4 / 256; i++)
                Hdst[tid + i * 256] = __ldcg(Hsrc + tid + i * 256);
        }
        __syncthreads();

        // ---- main loop: 8 batches x 8 cols per warp, packed f32x2 FMA ----
        unsigned long long V[32];   // V[(bb<<2)|jj2] = acc pair (jj=2*jj2, 2*jj2+1)
#pragma unroll
        for (int v = 0; v < 32; v++) V[v] = 0ull;

#pragma unroll
        for (int i = 0; i < 16; i++) {
            unsigned long long h2[8], w2[4];
#pragma unroll
            for (int b = 0; b < 8; b++)
                h2[b] = pack2(hp[b * H_ + i * 32]);
#pragma unroll
            for (int j2 = 0; j2 < 4; j2++)
                w2[j2] = *(const unsigned long long*)&wp[(size_t)i * 32 * WS_STRIDE + j2 * 2];
#pragma unroll
            for (int b = 0; b < 8; b++)
#pragma unroll
                for (int j2 = 0; j2 < 4; j2++)
                    V[(b << 2) | j2] = fma2(h2[b], w2[j2], V[(b << 2) | j2]);
        }

        // ---- split butterfly reduction over 32 k-lanes ----
        // value index bits: vi = (bb2,bb1,bb0,jj2hi,jj2lo); packed halves = jj parity
        unsigned s;
        // stage d=16: split bb1 (vi bit3)
        s = (lane >> 4) & 1;
        unsigned long long W1[16];
#pragma unroll
        for (int g = 0; g < 16; g++) {
            int vi = ((g >> 3) << 4) | (g & 7);
            unsigned long long snd = s ? V[vi] : V[vi | 8];
            unsigned long long kp  = s ? V[vi | 8] : V[vi];
            unsigned long long rcv = __shfl_xor_sync(0xffffffffu, snd, 16);
            W1[g] = add2(kp, rcv);
        }
        // stage d=8: split bb0 (bit2)
        s = (lane >> 3) & 1;
        unsigned long long W2r[8];
#pragma unroll
        for (int g = 0; g < 8; g++) {
            int vi = ((g >> 2) << 3) | (g & 3);
            unsigned long long snd = s ? W1[vi] : W1[vi | 4];
            unsigned long long kp  = s ? W1[vi | 4] : W1[vi];
            unsigned long long rcv = __shfl_xor_sync(0xffffffffu, snd, 8);
            W2r[g] = add2(kp, rcv);
        }
        // stage d=4: split jj2 bit1 (bit1)
        s = (lane >> 2) & 1;
        unsigned long long W3r[4];
#pragma unroll
        for (int g = 0; g < 4; g++) {
            int vi = ((g >> 1) << 2) | (g & 1);
            unsigned long long snd = s ? W2r[vi] : W2r[vi | 2];
            unsigned long long kp  = s ? W2r[vi | 2] : W2r[vi];
            unsigned long long rcv = __shfl_xor_sync(0xffffffffu, snd, 4);
            W3r[g] = add2(kp, rcv);
        }
        // stage d=2: split jj2 bit0 (bit0)
        s = (lane >> 1) & 1;
        unsigned long long W4r[2];
#pragma unroll
        for (int g = 0; g < 2; g++) {
            int vi = g << 1;
            unsigned long long snd = s ? W3r[vi] : W3r[vi | 1];
            unsigned long long kp  = s ? W3r[vi | 1] : W3r[vi];
            unsigned long long rcv = __shfl_xor_sync(0xffffffffu, snd, 2);
            W4r[g] = add2(kp, rcv);
        }
        // stage d=1: split jj parity (packed halves)
        s = lane & 1;
        float fin[2];
#pragma unroll
        for (int r = 0; r < 2; r++) {
            float lo, hi;
            unpack2(W4r[r], lo, hi);
            float snd = s ? lo : hi;
            float kp  = s ? hi : lo;
            float rcv = __shfl_xor_sync(0xffffffffu, snd, 1);
            fin[r] = kp + rcv;
        }
        // lane holds ids (lane) and (lane+32) for this (khalf, jt)
        {
            float* redw = red + khalf * RED_HALF + jt * RED_STRIDE;
            redw[lane]      = fin[0];
            redw[lane + 32] = fin[1];
        }
        __syncthreads();

        // ---- per-thread tail: combine k-halves, tanh, publish ----
        float v = red[cjt * RED_STRIDE + cid] + red[RED_HALF + cjt * RED_STRIDE + cid];
        float val = tanhf(v + xr);
        g_H[(t + 1) & 1][b0 + cb][j0 + cc] = val;

        // ---- per batch-group barrier: release flag (orders g_H), then poll ----
        __syncthreads();
        if (tid == 0) st_rel(&myflags[cg], (unsigned)(t + 1));

        // out[] stores are not read by anyone: issue AFTER the release so they
        // don't delay the flag.
        out[out_base + (size_t)t * H_] = val;
        if (write_last && t == S_ - 1)
            out[(size_t)B_ * S_ * H_ + (size_t)(b0 + cb) * H_ + j0 + cc] = val;

        if (tid < 32) {
            while (ld_acq(&myflags[tid]) < (unsigned)(t + 1)) { }
        }
        __syncthreads();
    }
}

// ---------------- launch ----------------
extern "C" void kernel_launch(void* const* d_in, const int* in_sizes, int n_in,
                              void* d_out, int out_size) {
    const float* X    = (const float*)d_in[0];
    const float* Wxh  = (const float*)d_in[1];
    const float* Whh  = (const float*)d_in[2];
    const float* bh   = (const float*)d_in[3];
    float* out        = (float*)d_out;

    rnn_init_kernel<<<64, 256>>>();

    dim3 gg(8, 256);
    gemm_xp_kernel<<<gg, 256>>>(X, Wxh, bh, out);

    cudaFuncSetAttribute(rnn_kernel,
                         cudaFuncAttributeMaxDynamicSharedMemorySize,
                         RNN_SMEM_BYTES);
    int write_last = (out_size >= B_ * S_ * H_ + B_ * H_) ? 1 : 0;
    rnn_kernel<<<128, 256, RNN_SMEM_BYTES>>>(Whh, out, write_last);
}

// round 4
// speedup vs baseline: 1.7318x; 1.0981x over previous
#include <cuda_runtime.h>
#include <math.h>

#define B_   32
#define S_   1024
#define IN_  1024
#define H_   1024

// ---------------- device scratch (no allocation allowed) ----------------
__device__ float    g_H[2][B_][H_];      // ping-pong hidden state
__device__ unsigned g_flags[4][32];      // per batch-group arrival flags (one 128B line per group)

// ---------------- helpers ----------------
__device__ __forceinline__ unsigned ld_acq(const unsigned* p) {
    unsigned v;
    asm volatile("ld.global.acquire.gpu.u32 %0, [%1];" : "=r"(v) : "l"(p));
    return v;
}
__device__ __forceinline__ void st_rel(unsigned* p, unsigned v) {
    asm volatile("st.global.release.gpu.u32 [%0], %1;" :: "l"(p), "r"(v));
}
__device__ __forceinline__ unsigned long long fma2(unsigned long long a,
                                                  unsigned long long b,
                                                  unsigned long long c) {
    unsigned long long d;
    asm("fma.rn.f32x2 %0, %1, %2, %3;" : "=l"(d) : "l"(a), "l"(b), "l"(c));
    return d;
}
__device__ __forceinline__ unsigned long long add2(unsigned long long a,
                                                   unsigned long long b) {
    unsigned long long d;
    asm("add.rn.f32x2 %0, %1, %2;" : "=l"(d) : "l"(a), "l"(b));
    return d;
}
__device__ __forceinline__ unsigned long long pack2(float x) {
    unsigned long long d;
    asm("mov.b64 %0, {%1, %1};" : "=l"(d) : "f"(x));
    return d;
}
__device__ __forceinline__ void unpack2(unsigned long long v, float& lo, float& hi) {
    asm("mov.b64 {%0, %1}, %2;" : "=f"(lo), "=f"(hi) : "l"(v));
}

// ---------------- init: zero H0 and flags ----------------
__global__ void rnn_init_kernel() {
    int idx = blockIdx.x * blockDim.x + threadIdx.x;
    int stride = gridDim.x * blockDim.x;
    float* p = &g_H[0][0][0];
    for (int i = idx; i < 2 * B_ * H_; i += stride) p[i] = 0.0f;
    if (idx < 128) ((unsigned*)g_flags)[idx] = 0u;
}

// ---------------- Xp = X @ W_xh + b  (fp32 SGEMM, 128x128x8 tiles, f32x2 FMA) ----------------
__global__ void __launch_bounds__(256, 2) gemm_xp_kernel(
    const float* __restrict__ A,    // [32768, 1024]
    const float* __restrict__ Bm,   // [1024, 1024]
    const float* __restrict__ bias, // [1024]
    float* __restrict__ C)          // [32768, 1024]
{
    __shared__ float As[8][128];    // transposed A tile
    __shared__ float Bs[8][128];

    int tid  = threadIdx.x;
    int brow = blockIdx.y * 128;
    int bcol = blockIdx.x * 128;

    int arow = tid >> 1;            // 0..127
    int acol = (tid & 1) * 4;       // 0 or 4
    int brl  = tid >> 5;            // 0..7
    int bc4  = (tid & 31) * 4;      // 0..124

    int ty = tid >> 4;              // 0..15
    int tx = tid & 15;              // 0..15

    unsigned long long acc2[8][4];
#pragma unroll
    for (int i = 0; i < 8; i++)
#pragma unroll
        for (int j = 0; j < 4; j++) acc2[i][j] = 0ull;

    const float* Aptr = A + (size_t)(brow + arow) * IN_ + acol;
    const float* Bptr = Bm + (size_t)brl * H_ + bcol + bc4;

    for (int k0 = 0; k0 < IN_; k0 += 8) {
        float4 a = *(const float4*)(Aptr + k0);
        As[acol + 0][arow] = a.x;
        As[acol + 1][arow] = a.y;
        As[acol + 2][arow] = a.z;
        As[acol + 3][arow] = a.w;
        *(float4*)&Bs[brl][bc4] = *(const float4*)(Bptr + (size_t)k0 * H_);
        __syncthreads();

#pragma unroll
        for (int k = 0; k < 8; k++) {
            float ar[8];
            *(float4*)(ar)     = *(float4*)&As[k][ty * 4];
            *(float4*)(ar + 4) = *(float4*)&As[k][64 + ty * 4];
            unsigned long long br2[4];
            br2[0] = *(const unsigned long long*)&Bs[k][tx * 4];
            br2[1] = *(const unsigned long long*)&Bs[k][tx * 4 + 2];
            br2[2] = *(const unsigned long long*)&Bs[k][64 + tx * 4];
            br2[3] = *(const unsigned long long*)&Bs[k][64 + tx * 4 + 2];
            unsigned long long ar2[8];
#pragma unroll
            for (int i = 0; i < 8; i++) ar2[i] = pack2(ar[i]);
#pragma unroll
            for (int i = 0; i < 8; i++)
#pragma unroll
                for (int j = 0; j < 4; j++)
                    acc2[i][j] = fma2(ar2[i], br2[j], acc2[i][j]);
        }
        __syncthreads();
    }

    // epilogue: add bias, store
    float4 bv0 = *(const float4*)&bias[bcol + tx * 4];
    float4 bv1 = *(const float4*)&bias[bcol + 64 + tx * 4];
    float bb[8] = {bv0.x, bv0.y, bv0.z, bv0.w, bv1.x, bv1.y, bv1.z, bv1.w};

#pragma unroll
    for (int i = 0; i < 8; i++) {
        int m = brow + ((i < 4) ? (ty * 4 + i) : (64 + ty * 4 + (i - 4)));
        float o[8];
        unpack2(acc2[i][0], o[0], o[1]);
        unpack2(acc2[i][1], o[2], o[3]);
        unpack2(acc2[i][2], o[4], o[5]);
        unpack2(acc2[i][3], o[6], o[7]);
        float4 o0, o1;
        o0.x = o[0] + bb[0]; o0.y = o[1] + bb[1];
        o0.z = o[2] + bb[2]; o0.w = o[3] + bb[3];
        o1.x = o[4] + bb[4]; o1.y = o[5] + bb[5];
        o1.z = o[6] + bb[6]; o1.w = o[7] + bb[7];
        *(float4*)&C[(size_t)m * H_ + bcol + tx * 4]      = o0;
        *(float4*)&C[(size_t)m * H_ + bcol + 64 + tx * 4] = o1;
    }
}

// ---------------- recurrent scan ----------------
// 128 CTAs = 4 batch-groups (8 batches each) x 32 col-groups (32 cols each).
// W_hh slice resident in SMEM (k-major, stride 34 -> conflict-free LDS.64 pairs).
// Per warp: 8 batches x 8 cols register tile, k split lane(32) x khalf(2).
#define WS_STRIDE  34
#define WS_FLOATS  (H_ * WS_STRIDE)          // 34816
#define HS_FLOATS  (8 * H_)                  // 8192
#define RED_STRIDE 72
#define RED_HALF   (4 * RED_STRIDE)          // 288
#define RED_FLOATS (2 * RED_HALF)            // 576
#define RNN_SMEM_BYTES ((WS_FLOATS + HS_FLOATS + RED_FLOATS) * 4)

extern __shared__ float rnn_smem[];

__global__ void __launch_bounds__(256, 1) rnn_kernel(
    const float* __restrict__ Whh,   // [1024, 1024]
    float* __restrict__ out,         // [B, S, H] holds Xp on entry, H_t on exit
    int write_last)
{
    float* Ws  = rnn_smem;                        // [1024][34]  Ws[k][j]
    float* Hs  = rnn_smem + WS_FLOATS;            // [8][1024]
    float* red = rnn_smem + WS_FLOATS + HS_FLOATS;// [2][4][72]

    int tid = threadIdx.x;
    int cta = blockIdx.x;
    int bg  = cta >> 5;      // batch group 0..3
    int cg  = cta & 31;      // col group 0..31
    int b0  = bg * 8;
    int j0  = cg * 32;

    // Preload W_hh slice: Ws[k][j] = Whh[k][j0+j] (k-major, stride 34).
    {
        int j = tid & 31;
        for (int k = tid >> 5; k < H_; k += 8)
            Ws[k * WS_STRIDE + j] = Whh[(size_t)k * H_ + j0 + j];
    }

    int warp  = tid >> 5;
    int lane  = tid & 31;
    int jt    = warp >> 1;        // j-tile 0..3 (8 cols each)
    int khalf = warp & 1;         // k-half 0/1
    int kbase = khalf * 512;

    unsigned* myflags = g_flags[bg];

    // consumer mapping: thread owns output (b0+cb, j0+cc)
    int cb = tid >> 5;            // 0..7
    int cc = tid & 31;            // 0..31
    int cjt = cc >> 3;
    int cid = cb * 8 + (cc & 7);
    size_t out_base = ((size_t)(b0 + cb) * S_) * H_ + j0 + cc;   // + t*H_ per step

    const float* hp = Hs + kbase + lane;
    const float* wp = Ws + (size_t)(kbase + lane) * WS_STRIDE + jt * 8;

    __syncthreads();   // Ws ready

    for (int t = 0; t < S_; t++) {
        // ---- prefetch Xp(t) for this thread's output (DRAM latency hidden by compute) ----
        float xr = __ldcg(&out[out_base + (size_t)t * H_]);

        // ---- stage H rows for our 8 batches (L2, bypass L1) ----
        {
            const float4* Hsrc = (const float4*)(&g_H[t & 1][b0][0]);
            float4* Hdst = (float4*)Hs;
#pragma unroll
            for (int i = 0; i < HS_FLOATS / 4 / 256; i++)
                Hdst[tid + i * 256] = __ldcg(Hsrc + tid + i * 256);
        }
        __syncthreads();

        // ---- main loop: 8 batches x 8 cols per warp, packed f32x2 FMA ----
        unsigned long long V[32];   // V[(bb<<2)|jj2] = acc pair (jj=2*jj2, 2*jj2+1)
#pragma unroll
        for (int v = 0; v < 32; v++) V[v] = 0ull;

#pragma unroll
        for (int i = 0; i < 16; i++) {
            unsigned long long h2[8], w2[4];
#pragma unroll
            for (int b = 0; b < 8; b++)
                h2[b] = pack2(hp[b * H_ + i * 32]);
#pragma unroll
            for (int j2 = 0; j2 < 4; j2++)
                w2[j2] = *(const unsigned long long*)&wp[(size_t)i * 32 * WS_STRIDE + j2 * 2];
#pragma unroll
            for (int b = 0; b < 8; b++)
#pragma unroll
                for (int j2 = 0; j2 < 4; j2++)
                    V[(b << 2) | j2] = fma2(h2[b], w2[j2], V[(b << 2) | j2]);
        }

        // ---- split butterfly reduction over 32 k-lanes ----
        // value index bits: vi = (bb2,bb1,bb0,jj2hi,jj2lo); packed halves = jj parity
        unsigned s;
        // stage d=16: split bb1 (vi bit3)
        s = (lane >> 4) & 1;
        unsigned long long W1[16];
#pragma unroll
        for (int g = 0; g < 16; g++) {
            int vi = ((g >> 3) << 4) | (g & 7);
            unsigned long long snd = s ? V[vi] : V[vi | 8];
            unsigned long long kp  = s ? V[vi | 8] : V[vi];
            unsigned long long rcv = __shfl_xor_sync(0xffffffffu, snd, 16);
            W1[g] = add2(kp, rcv);
        }
        // stage d=8: split bb0 (bit2)
        s = (lane >> 3) & 1;
        unsigned long long W2r[8];
#pragma unroll
        for (int g = 0; g < 8; g++) {
            int vi = ((g >> 2) << 3) | (g & 3);
            unsigned long long snd = s ? W1[vi] : W1[vi | 4];
            unsigned long long kp  = s ? W1[vi | 4] : W1[vi];
            unsigned long long rcv = __shfl_xor_sync(0xffffffffu, snd, 8);
            W2r[g] = add2(kp, rcv);
        }
        // stage d=4: split jj2 bit1 (bit1)
        s = (lane >> 2) & 1;
        unsigned long long W3r[4];
#pragma unroll
        for (int g = 0; g < 4; g++) {
            int vi = ((g >> 1) << 2) | (g & 1);
            unsigned long long snd = s ? W2r[vi] : W2r[vi | 2];
            unsigned long long kp  = s ? W2r[vi | 2] : W2r[vi];
            unsigned long long rcv = __shfl_xor_sync(0xffffffffu, snd, 4);
            W3r[g] = add2(kp, rcv);
        }
        // stage d=2: split jj2 bit0 (bit0)
        s = (lane >> 1) & 1;
        unsigned long long W4r[2];
#pragma unroll
        for (int g = 0; g < 2; g++) {
            int vi = g << 1;
            unsigned long long snd = s ? W3r[vi] : W3r[vi | 1];
            unsigned long long kp  = s ? W3r[vi | 1] : W3r[vi];
            unsigned long long rcv = __shfl_xor_sync(0xffffffffu, snd, 2);
            W4r[g] = add2(kp, rcv);
        }
        // stage d=1: split jj parity (packed halves)
        s = lane & 1;
        float fin[2];
#pragma unroll
        for (int r = 0; r < 2; r++) {
            float lo, hi;
            unpack2(W4r[r], lo, hi);
            float snd = s ? lo : hi;
            float kp  = s ? hi : lo;
            float rcv = __shfl_xor_sync(0xffffffffu, snd, 1);
            fin[r] = kp + rcv;
        }
        // lane holds ids (lane) and (lane+32) for this (khalf, jt)
        {
            float* redw = red + khalf * RED_HALF + jt * RED_STRIDE;
            redw[lane]      = fin[0];
            redw[lane + 32] = fin[1];
        }
        __syncthreads();

        // ---- per-thread tail: combine k-halves, tanh, publish ----
        float v = red[cjt * RED_STRIDE + cid] + red[RED_HALF + cjt * RED_STRIDE + cid];
        float val = tanhf(v + xr);
        g_H[(t + 1) & 1][b0 + cb][j0 + cc] = val;

        // ---- per batch-group barrier: release flag (orders g_H), then poll ----
        __syncthreads();
        if (tid == 0) st_rel(&myflags[cg], (unsigned)(t + 1));

        // out[] stores are not read by anyone: issue AFTER the release so they
        // don't delay the flag.
        out[out_base + (size_t)t * H_] = val;
        if (write_last && t == S_ - 1)
            out[(size_t)B_ * S_ * H_ + (size_t)(b0 + cb) * H_ + j0 + cc] = val;

        if (tid < 32) {
            while (ld_acq(&myflags[tid]) < (unsigned)(t + 1)) { }
        }
        __syncthreads();
    }
}

// ---------------- launch ----------------
extern "C" void kernel_launch(void* const* d_in, const int* in_sizes, int n_in,
                              void* d_out, int out_size) {
    const float* X    = (const float*)d_in[0];
    const float* Wxh  = (const float*)d_in[1];
    const float* Whh  = (const float*)d_in[2];
    const float* bh   = (const float*)d_in[3];
    float* out        = (float*)d_out;

    rnn_init_kernel<<<64, 256>>>();

    dim3 gg(8, 256);
    gemm_xp_kernel<<<gg, 256>>>(X, Wxh, bh, out);

    cudaFuncSetAttribute(rnn_kernel,
                         cudaFuncAttributeMaxDynamicSharedMemorySize,
                         RNN_SMEM_BYTES);
    int write_last = (out_size >= B_ * S_ * H_ + B_ * H_) ? 1 : 0;
    rnn_kernel<<<128, 256, RNN_SMEM_BYTES>>>(Whh, out, write_last);
}